// round 1
// baseline (speedup 1.0000x reference)
#include <cuda_runtime.h>
#include <cstdint>
#include <cmath>

// Problem constants (fixed shapes)
#define Nn 8192
#define Dd 64
#define Pp 32
#define Tt 1
#define Mm 50
#define Hh 512
#define KX 96          // D + P (the s-column is folded into acc init)

// Kernel tiling
#define Rr 64          // rows per block
#define NBLOCKS (Nn / Rr)   // 128
#define THREADS 256
#define CHUNK 64       // h columns processed per chunk
#define NCHUNK (Hh / CHUNK) // 8
#define XS 97          // sXin row stride (96 cols + 1 pad, odd -> conflict-free)
#define HS 68          // sH row stride (64 + 4 pad; 4*68 mod 32 = 16, float4-aligned)

typedef unsigned long long u64;

// ---- packed dual-FP32 helpers (sm_103a f32x2 pipe) ----
__device__ __forceinline__ u64 pk2(float lo, float hi) {
    u64 r; asm("mov.b64 %0, {%1,%2};" : "=l"(r) : "f"(lo), "f"(hi)); return r;
}
__device__ __forceinline__ void upk2(u64 v, float& lo, float& hi) {
    asm("mov.b64 {%0,%1}, %2;" : "=f"(lo), "=f"(hi) : "l"(v));
}
__device__ __forceinline__ u64 ffma2(u64 a, u64 b, u64 c) {
    u64 d; asm("fma.rn.f32x2 %0, %1, %2, %3;" : "=l"(d) : "l"(a), "l"(b), "l"(c)); return d;
}
__device__ __forceinline__ float fast_tanh(float x) {
    float y; asm("tanh.approx.f32 %0, %1;" : "=f"(y) : "f"(x)); return y;
}

__global__ void __launch_bounds__(THREADS, 1) sim_rollout_kernel(
    const float* __restrict__ X0, const float* __restrict__ V0,
    const float* __restrict__ Y,  const float* __restrict__ theta,
    const float* __restrict__ W1, const float* __restrict__ b1,
    const float* __restrict__ W2, const float* __restrict__ b2,
    const float* __restrict__ noise, const int* __restrict__ obs_index,
    float* __restrict__ out)
{
    __shared__ __align__(16) float sXin[Rr * XS];  // [X (0..63) | Yt (64..95)] per row
    __shared__ __align__(16) float sH[Rr * HS];    // current 64-col h chunk

    const int tid  = threadIdx.x;
    const int cg   = tid & 15;   // column group 0..15 (4 cols each)
    const int rg   = tid >> 4;   // row group    0..15 (4 rows each)
    const int row0 = blockIdx.x * Rr;

    const float dt   = 1.0f / (float)Mm;
    const float sqdt = sqrtf(dt);

    const int obs = *obs_index;

    // ---- load persistent state into smem ----
    for (int idx = tid; idx < Rr * Dd; idx += THREADS) {
        int r = idx >> 6, d = idx & 63;
        sXin[r * XS + d] = X0[(row0 + r) * Dd + d];
    }
    for (int idx = tid; idx < Rr * Pp; idx += THREADS) {
        int r = idx >> 5, p = idx & 31;
        sXin[r * XS + 64 + p] = Y[(row0 + r) * (Tt * Pp) + obs * Pp + p];
    }

    float vreg[4];
    #pragma unroll
    for (int i = 0; i < 4; i++) vreg[i] = V0[row0 + rg * 4 + i];

    const float4 thv = *(const float4*)(theta + cg * 4);
    const float4 b2v = *(const float4*)(b2 + cg * 4);

    __syncthreads();

    // ---- 50-step rollout, all in-block ----
    for (int m = 0; m < Mm; ++m) {
        const float s = (float)m * dt;

        // prefetch this step's noise (DRAM latency hidden behind the GEMMs)
        float4 nz[4];
        const float* nbase = noise + ((size_t)m * Nn + row0) * Dd;
        #pragma unroll
        for (int i = 0; i < 4; i++)
            nz[i] = *(const float4*)(nbase + (rg * 4 + i) * Dd + cg * 4);

        u64 zacc[4][2];   // Z micro-tile: 4 rows x 4 cols (2 f32x2 pairs)
        #pragma unroll
        for (int i = 0; i < 4; i++) { zacc[i][0] = 0ull; zacc[i][1] = 0ull; }

        for (int ch = 0; ch < NCHUNK; ++ch) {
            const int c0 = ch * CHUNK + cg * 4;

            // acc init = s * W1[0][c0..c0+3]  (uniform s-column folded in)
            float4 w0 = *(const float4*)(W1 + c0);
            const u64 sp = pk2(s, s);
            u64 ia0 = ffma2(sp, pk2(w0.x, w0.y), 0ull);
            u64 ia1 = ffma2(sp, pk2(w0.z, w0.w), 0ull);
            u64 acc[4][2];
            #pragma unroll
            for (int i = 0; i < 4; i++) { acc[i][0] = ia0; acc[i][1] = ia1; }

            // GEMM1: h_chunk[64x64] = Xin[64x96] @ W1[1..96][chunk]
            const float* w1p = W1 + Hh + c0;       // row k+1, this thread's 4 cols
            const float* ap0 = sXin + rg * 4 * XS;
            #pragma unroll 8
            for (int k = 0; k < KX; ++k) {
                float4 b = *(const float4*)(w1p + (size_t)k * Hh);
                u64 bp0 = pk2(b.x, b.y);
                u64 bp1 = pk2(b.z, b.w);
                #pragma unroll
                for (int i = 0; i < 4; i++) {
                    float a = ap0[i * XS + k];     // smem broadcast
                    u64 ap = pk2(a, a);
                    acc[i][0] = ffma2(ap, bp0, acc[i][0]);
                    acc[i][1] = ffma2(ap, bp1, acc[i][1]);
                }
            }

            // bias + tanh -> sH
            float4 b1v = *(const float4*)(b1 + c0);
            #pragma unroll
            for (int i = 0; i < 4; i++) {
                float x0, x1, x2, x3;
                upk2(acc[i][0], x0, x1);
                upk2(acc[i][1], x2, x3);
                float4 hv;
                hv.x = fast_tanh(x0 + b1v.x);
                hv.y = fast_tanh(x1 + b1v.y);
                hv.z = fast_tanh(x2 + b1v.z);
                hv.w = fast_tanh(x3 + b1v.w);
                *(float4*)(sH + (rg * 4 + i) * HS + cg * 4) = hv;
            }
            __syncthreads();

            // GEMM2 partial: Z[64x64] += h_chunk[64x64] @ W2[chunk][64]
            const float* w2p = W2 + (ch * CHUNK) * Dd + cg * 4;
            const float* hp0 = sH + rg * 4 * HS;
            #pragma unroll 8
            for (int k = 0; k < CHUNK; ++k) {
                float4 b = *(const float4*)(w2p + k * Dd);
                u64 bp0 = pk2(b.x, b.y);
                u64 bp1 = pk2(b.z, b.w);
                #pragma unroll
                for (int i = 0; i < 4; i++) {
                    float a = hp0[i * HS + k];
                    u64 ap = pk2(a, a);
                    zacc[i][0] = ffma2(ap, bp0, zacc[i][0]);
                    zacc[i][1] = ffma2(ap, bp1, zacc[i][1]);
                }
            }
            __syncthreads();   // before next chunk overwrites sH
        }

        // ---- epilogue: V drift/diffusion + X update ----
        float vpart[4];
        #pragma unroll
        for (int i = 0; i < 4; i++) {
            float z0, z1, z2, z3;
            upk2(zacc[i][0], z0, z1);
            upk2(zacc[i][1], z2, z3);
            z0 += b2v.x; z1 += b2v.y; z2 += b2v.z; z3 += b2v.w;

            float wm0 = sqdt * nz[i].x, wm1 = sqdt * nz[i].y;
            float wm2 = sqdt * nz[i].z, wm3 = sqdt * nz[i].w;

            // drift_V = 0.5||Z||^2 + (-Z).Z = -0.5||Z||^2 ;  dV = dt*drift_V + Z.Wm
            vpart[i] = (z0 * wm0 + z1 * wm1 + z2 * wm2 + z3 * wm3)
                     - 0.5f * dt * (z0 * z0 + z1 * z1 + z2 * z2 + z3 * z3);

            // X_new = X + dt*(theta - X - Z) + Wm   (SIGMA = 1)
            float* xp = sXin + (rg * 4 + i) * XS + cg * 4;
            float xo0 = xp[0], xo1 = xp[1], xo2 = xp[2], xo3 = xp[3];
            xp[0] = xo0 + dt * (thv.x - xo0 - z0) + wm0;
            xp[1] = xo1 + dt * (thv.y - xo1 - z1) + wm1;
            xp[2] = xo2 + dt * (thv.z - xo2 - z2) + wm2;
            xp[3] = xo3 + dt * (thv.w - xo3 - z3) + wm3;
        }

        // reduce V partials across the 16 column-group lanes
        #pragma unroll
        for (int i = 0; i < 4; i++) {
            float v = vpart[i];
            v += __shfl_down_sync(0xffffffffu, v, 8, 16);
            v += __shfl_down_sync(0xffffffffu, v, 4, 16);
            v += __shfl_down_sync(0xffffffffu, v, 2, 16);
            v += __shfl_down_sync(0xffffffffu, v, 1, 16);
            if (cg == 0) vreg[i] += v;
        }
        __syncthreads();   // X writes visible before next step's GEMM1
    }

    // ---- write out: X then V ----
    float* outX = out;
    float* outV = out + (size_t)Nn * Dd;
    for (int idx = tid; idx < Rr * Dd; idx += THREADS) {
        int r = idx >> 6, d = idx & 63;
        outX[(row0 + r) * Dd + d] = sXin[r * XS + d];
    }
    if (cg == 0) {
        #pragma unroll
        for (int i = 0; i < 4; i++)
            outV[row0 + rg * 4 + i] = vreg[i];
    }
}

extern "C" void kernel_launch(void* const* d_in, const int* in_sizes, int n_in,
                              void* d_out, int out_size)
{
    (void)in_sizes; (void)n_in; (void)out_size;
    sim_rollout_kernel<<<NBLOCKS, THREADS>>>(
        (const float*)d_in[0],   // X0
        (const float*)d_in[1],   // V0
        (const float*)d_in[2],   // Y
        (const float*)d_in[3],   // theta
        (const float*)d_in[4],   // W1
        (const float*)d_in[5],   // b1
        (const float*)d_in[6],   // W2
        (const float*)d_in[7],   // b2
        (const float*)d_in[8],   // noise
        (const int*)d_in[9],     // obs_index
        (float*)d_out);
}

// round 2
// speedup vs baseline: 1.6279x; 1.6279x over previous
#include <cuda_runtime.h>
#include <cstdint>
#include <cmath>

// ---------------- problem constants ----------------
#define Nn 8192
#define Dd 64
#define Pp 32
#define Mm 50
#define Hh 512
#define KX 96              // D + P  (s column folded separately)

// ---------------- tiling ----------------
#define Rr 64              // rows per CTA
#define NBLOCKS (Nn / Rr)  // 128
#define THREADS 256
#define CHUNK 64           // H columns per chunk
#define NCHUNK (Hh / CHUNK)

// padded strides (floats); all ≡ 4 (mod 32) and multiples of 4 -> 16B aligned,
// conflict-free v2.b64 loads for consecutive rows/cols
#define XS 100             // sX row stride   (96 cols + pad)
#define HS 68              // sH row stride   (64 cols + pad)
#define W1S 100            // W1t image: [64 c][100]  per chunk
#define W1IMG (CHUNK * W1S)      // 6400 floats per chunk image
#define W2S 516            // W2t: [64 d][516]
#define W2SZ (Dd * W2S)          // 33024 floats

// smem layout (float offsets)
#define OFF_W2T 0
#define OFF_W1  (OFF_W2T + W2SZ)          // 33024  (2 buffers)
#define OFF_X   (OFF_W1 + 2 * W1IMG)      // 45824
#define OFF_H   (OFF_X + Rr * XS)         // 52224
#define OFF_B1  (OFF_H + Rr * HS)         // 56576
#define OFF_W0  (OFF_B1 + Hh)             // 57088
#define OFF_V   (OFF_W0 + Hh)             // 57600
#define SMEM_FLOATS (OFF_V + Rr)          // 57664
#define SMEM_BYTES (SMEM_FLOATS * 4)      // 230656

typedef unsigned long long u64;

// global scratch for transposed weights (no runtime allocation allowed)
__device__ float gW1t[NCHUNK * W1IMG];    // [chunk][c][k]   k in 0..95 (pad to 100)
__device__ float gW2t[W2SZ];              // [d][k]          k in 0..511 (pad to 516)

// ---------------- helpers ----------------
__device__ __forceinline__ void fma2(u64& acc, u64 a, u64 b) {
    asm("fma.rn.f32x2 %0, %1, %2, %0;" : "+l"(acc) : "l"(a), "l"(b));
}
__device__ __forceinline__ float2 upk(u64 v) {
    float2 r; asm("mov.b64 {%0,%1}, %2;" : "=f"(r.x), "=f"(r.y) : "l"(v)); return r;
}
__device__ __forceinline__ float fast_tanh(float x) {
    float y; asm("tanh.approx.f32 %0, %1;" : "=f"(y) : "f"(x)); return y;
}
__device__ __forceinline__ void cp16(uint32_t dst, const float* src) {
    asm volatile("cp.async.cg.shared.global [%0], [%1], 16;" :: "r"(dst), "l"(src));
}
#define CP_COMMIT() asm volatile("cp.async.commit_group;")
#define CP_WAIT1()  asm volatile("cp.async.wait_group 1;")

// ---------------- setup: transpose weights into padded k-contiguous images ----
__global__ void transpose_weights(const float* __restrict__ W1,
                                  const float* __restrict__ W2) {
    int tid = blockIdx.x * blockDim.x + threadIdx.x;
    int stride = gridDim.x * blockDim.x;
    // W1t[ch][c][k] = W1[k+1][ch*64 + c]
    for (int i = tid; i < NCHUNK * CHUNK * KX; i += stride) {
        int ch = i / (CHUNK * KX);
        int r  = i % (CHUNK * KX);
        int c  = r / KX;
        int k  = r % KX;
        gW1t[ch * W1IMG + c * W1S + k] = W1[(size_t)(k + 1) * Hh + ch * CHUNK + c];
    }
    // W2t[d][k] = W2[k][d]
    for (int i = tid; i < Dd * Hh; i += stride) {
        int d = i / Hh;
        int k = i % Hh;
        gW2t[d * W2S + k] = W2[(size_t)k * Dd + d];
    }
}

// ---------------- main persistent rollout kernel ----------------
__global__ void __launch_bounds__(THREADS, 1) sim_rollout_kernel(
    const float* __restrict__ X0, const float* __restrict__ V0,
    const float* __restrict__ Y,  const float* __restrict__ theta,
    const float* __restrict__ W1, const float* __restrict__ b1,
    const float* __restrict__ W2, const float* __restrict__ b2,
    const float* __restrict__ noise, const int* __restrict__ obs_index,
    float* __restrict__ out)
{
    extern __shared__ float sm[];
    float* sW2t = sm + OFF_W2T;
    float* sW1  = sm + OFF_W1;
    float* sX   = sm + OFF_X;
    float* sH   = sm + OFF_H;
    float* sB1  = sm + OFF_B1;
    float* sW0  = sm + OFF_W0;
    float* sV   = sm + OFF_V;

    const int tid = threadIdx.x;
    const int w   = tid >> 5;
    const int l   = tid & 31;
    const int row0 = blockIdx.x * Rr;

    // warp tile: 16 rows x 32 cols; thread: 4 rows (stride 4) x 4 cols (stride 8)
    const int r0 = ((w >> 1) << 4) + (l >> 3);   // thread row base; rows r0+4i
    const int cb = ((w & 1) << 5) + (l & 7);     // thread col base; cols cb+8j

    const float dt   = 1.0f / (float)Mm;
    const float sqdt = sqrtf(dt);
    const int obs = *obs_index;

    // ---- one-time staging ----
    // W2t -> smem (reused all 50 steps)
    for (int idx = tid; idx < W2SZ / 4; idx += THREADS)
        ((float4*)sW2t)[idx] = ((const float4*)gW2t)[idx];
    // state
    for (int idx = tid; idx < Rr * Dd; idx += THREADS) {
        int r = idx >> 6, d = idx & 63;
        sX[r * XS + d] = X0[(size_t)(row0 + r) * Dd + d];
    }
    for (int idx = tid; idx < Rr * Pp; idx += THREADS) {
        int r = idx >> 5, p = idx & 31;
        sX[r * XS + 64 + p] = Y[(size_t)(row0 + r) * Pp + obs * Pp + p];
    }
    for (int idx = tid; idx < Hh; idx += THREADS) {
        sB1[idx] = b1[idx];
        sW0[idx] = W1[idx];         // W1 row 0 (the s column weights)
    }
    if (tid < Rr) sV[tid] = V0[row0 + tid];

    // per-thread column constants
    float thc[4], b2c[4];
    #pragma unroll
    for (int j = 0; j < 4; j++) {
        thc[j] = theta[cb + 8 * j];
        b2c[j] = b2[cb + 8 * j];
    }

    // prime cp.async: chunk 0 -> buffer 0
    const uint32_t w1sa = (uint32_t)__cvta_generic_to_shared(sW1);
    for (int idx = tid; idx < W1IMG / 4; idx += THREADS)
        cp16(w1sa + idx * 16, gW1t + idx * 4);
    CP_COMMIT();

    const float* aP1 = sX + r0 * XS;
    const float* aP2 = sH + r0 * HS;

    // ---- 50-step rollout ----
    for (int m = 0; m < Mm; ++m) {
        const float s = (float)m * dt;

        // prefetch this step's noise
        float nz[4][4];
        const float* nb = noise + ((size_t)m * Nn + row0) * Dd;
        #pragma unroll
        for (int i = 0; i < 4; i++)
            #pragma unroll
            for (int j = 0; j < 4; j++)
                nz[i][j] = nb[(size_t)(r0 + 4 * i) * Dd + cb + 8 * j];

        u64 zacc[4][4];
        #pragma unroll
        for (int i = 0; i < 4; i++)
            #pragma unroll
            for (int j = 0; j < 4; j++) zacc[i][j] = 0ull;

        for (int ch = 0; ch < NCHUNK; ++ch) {
            // issue prefetch of next chunk into the other buffer
            {
                int nxt = (ch + 1) & 7;
                uint32_t dst = w1sa + (uint32_t)(((ch + 1) & 1) * W1IMG) * 4u;
                const float* src = gW1t + nxt * W1IMG;
                for (int idx = tid; idx < W1IMG / 4; idx += THREADS)
                    cp16(dst + idx * 16, src + idx * 4);
                CP_COMMIT();
            }
            CP_WAIT1();          // current buffer's group retired
            __syncthreads();     // buffer visible; prev GEMM2 done with sH; X updates visible

            const float* w1b = sW1 + (ch & 1) * W1IMG + cb * W1S;

            // per-chunk column constants (s*W0 + b1)
            float hb[4];
            #pragma unroll
            for (int j = 0; j < 4; j++) {
                int c = ch * CHUNK + cb + 8 * j;
                hb[j] = s * sW0[c] + sB1[c];
            }

            // ---- GEMM1: h = Xin[64x96] @ W1chunk  (f32x2 pairs over k) ----
            u64 acc[4][4];
            #pragma unroll
            for (int i = 0; i < 4; i++)
                #pragma unroll
                for (int j = 0; j < 4; j++) acc[i][j] = 0ull;

            #pragma unroll 8
            for (int q = 0; q < KX / 4; ++q) {
                ulonglong2 A[4], B[4];
                #pragma unroll
                for (int i = 0; i < 4; i++)
                    A[i] = *(const ulonglong2*)(aP1 + i * 4 * XS + q * 4);
                #pragma unroll
                for (int j = 0; j < 4; j++)
                    B[j] = *(const ulonglong2*)(w1b + j * 8 * W1S + q * 4);
                #pragma unroll
                for (int i = 0; i < 4; i++)
                    #pragma unroll
                    for (int j = 0; j < 4; j++) {
                        fma2(acc[i][j], A[i].x, B[j].x);
                        fma2(acc[i][j], A[i].y, B[j].y);
                    }
            }

            // bias + tanh -> sH
            #pragma unroll
            for (int i = 0; i < 4; i++)
                #pragma unroll
                for (int j = 0; j < 4; j++) {
                    float2 t = upk(acc[i][j]);
                    float h = fast_tanh(t.x + t.y + hb[j]);
                    sH[(r0 + 4 * i) * HS + cb + 8 * j] = h;
                }
            __syncthreads();

            // ---- GEMM2: Z += h[64x64] @ W2chunk ----
            const float* w2b = sW2t + cb * W2S + ch * CHUNK;
            #pragma unroll 8
            for (int q = 0; q < CHUNK / 4; ++q) {
                ulonglong2 A[4], B[4];
                #pragma unroll
                for (int i = 0; i < 4; i++)
                    A[i] = *(const ulonglong2*)(aP2 + i * 4 * HS + q * 4);
                #pragma unroll
                for (int j = 0; j < 4; j++)
                    B[j] = *(const ulonglong2*)(w2b + j * 8 * W2S + q * 4);
                #pragma unroll
                for (int i = 0; i < 4; i++)
                    #pragma unroll
                    for (int j = 0; j < 4; j++) {
                        fma2(zacc[i][j], A[i].x, B[j].x);
                        fma2(zacc[i][j], A[i].y, B[j].y);
                    }
            }
        }

        // ---- epilogue: V and X updates ----
        #pragma unroll
        for (int i = 0; i < 4; i++) {
            float vpart = 0.0f;
            #pragma unroll
            for (int j = 0; j < 4; j++) {
                float2 t = upk(zacc[i][j]);
                float z  = t.x + t.y + b2c[j];
                float wm = sqdt * nz[i][j];
                vpart += z * wm - 0.5f * dt * z * z;
                float* xp = &sX[(r0 + 4 * i) * XS + cb + 8 * j];
                float xo = *xp;
                *xp = xo + dt * (thc[j] - xo - z) + wm;
            }
            // reduce over the 8 lanes sharing this row (l&7 groups)
            vpart += __shfl_down_sync(0xffffffffu, vpart, 4, 8);
            vpart += __shfl_down_sync(0xffffffffu, vpart, 2, 8);
            vpart += __shfl_down_sync(0xffffffffu, vpart, 1, 8);
            if ((l & 7) == 0) atomicAdd(&sV[r0 + 4 * i], vpart);
        }
        // next iteration's chunk-0 __syncthreads orders X/V before reuse
    }

    __syncthreads();
    // ---- output: X then V ----
    for (int idx = tid; idx < Rr * Dd; idx += THREADS) {
        int r = idx >> 6, d = idx & 63;
        out[(size_t)(row0 + r) * Dd + d] = sX[r * XS + d];
    }
    if (tid < Rr) out[(size_t)Nn * Dd + row0 + tid] = sV[tid];
}

extern "C" void kernel_launch(void* const* d_in, const int* in_sizes, int n_in,
                              void* d_out, int out_size)
{
    (void)in_sizes; (void)n_in; (void)out_size;
    const float* X0    = (const float*)d_in[0];
    const float* V0    = (const float*)d_in[1];
    const float* Yv    = (const float*)d_in[2];
    const float* theta = (const float*)d_in[3];
    const float* W1    = (const float*)d_in[4];
    const float* b1    = (const float*)d_in[5];
    const float* W2    = (const float*)d_in[6];
    const float* b2    = (const float*)d_in[7];
    const float* noise = (const float*)d_in[8];
    const int*   obs   = (const int*)d_in[9];

    cudaFuncSetAttribute(sim_rollout_kernel,
                         cudaFuncAttributeMaxDynamicSharedMemorySize, SMEM_BYTES);

    transpose_weights<<<64, 256>>>(W1, W2);
    sim_rollout_kernel<<<NBLOCKS, THREADS, SMEM_BYTES>>>(
        X0, V0, Yv, theta, W1, b1, W2, b2, noise, obs, (float*)d_out);
}

// round 3
// speedup vs baseline: 1.6449x; 1.0104x over previous
#include <cuda_runtime.h>
#include <cstdint>
#include <cmath>

// ---------------- problem constants ----------------
#define Nn 8192
#define Dd 64
#define Pp 32
#define Mm 50
#define Hh 512
#define KX 96              // D + P  (s column folded separately)

// ---------------- tiling ----------------
#define Rr 64              // rows per CTA
#define NBLOCKS (Nn / Rr)  // 128
#define THREADS 256
#define CHUNK 64           // H columns per chunk
#define NCHUNK (Hh / CHUNK)

// padded strides (floats); all ≡ 4 (mod 32) and ≡ 0 (mod 4) -> 16B-aligned rows,
// conflict-free LDS.128 with lane-stride-16 column mapping
#define XS 100             // sX row stride   (96 cols + pad)
#define HS 68              // sH row stride   (64 cols + pad)
#define W1S 100            // W1t image: [64 c][100] per chunk
#define W1IMG (CHUNK * W1S)      // 6400 floats per chunk image
#define W2S 516            // W2t: [64 d][516]
#define W2SZ (Dd * W2S)          // 33024 floats

// smem layout (float offsets)
#define OFF_W2T 0
#define OFF_W1  (OFF_W2T + W2SZ)          // 33024  (2 buffers)
#define OFF_X   (OFF_W1 + 2 * W1IMG)      // 45824
#define OFF_H   (OFF_X + Rr * XS)         // 52224
#define OFF_B1  (OFF_H + Rr * HS)         // 56576
#define OFF_W0  (OFF_B1 + Hh)             // 57088
#define SMEM_FLOATS (OFF_W0 + Hh)         // 57600
#define SMEM_BYTES (SMEM_FLOATS * 4)      // 230400

typedef unsigned long long u64;

// global scratch for transposed weights (no runtime allocation allowed)
__device__ float gW1t[NCHUNK * W1IMG];    // [chunk][c][k]   k 0..95 (pad 100)
__device__ float gW2t[W2SZ];              // [d][k]          k 0..511 (pad 516)

// ---------------- helpers ----------------
__device__ __forceinline__ void fma2(u64& acc, u64 a, u64 b) {
    asm("fma.rn.f32x2 %0, %1, %2, %0;" : "+l"(acc) : "l"(a), "l"(b));
}
__device__ __forceinline__ float2 upk(u64 v) {
    float2 r; asm("mov.b64 {%0,%1}, %2;" : "=f"(r.x), "=f"(r.y) : "l"(v)); return r;
}
__device__ __forceinline__ float fast_tanh(float x) {
    float y; asm("tanh.approx.f32 %0, %1;" : "=f"(y) : "f"(x)); return y;
}
__device__ __forceinline__ void cp16(uint32_t dst, const float* src) {
    asm volatile("cp.async.cg.shared.global [%0], [%1], 16;" :: "r"(dst), "l"(src));
}
#define CP_COMMIT() asm volatile("cp.async.commit_group;")
#define CP_WAIT1()  asm volatile("cp.async.wait_group 1;")

// ---------------- setup: transpose weights ----------------
__global__ void transpose_weights(const float* __restrict__ W1,
                                  const float* __restrict__ W2) {
    int tid = blockIdx.x * blockDim.x + threadIdx.x;
    int stride = gridDim.x * blockDim.x;
    for (int i = tid; i < NCHUNK * CHUNK * KX; i += stride) {
        int ch = i / (CHUNK * KX);
        int r  = i % (CHUNK * KX);
        int c  = r / KX;
        int k  = r % KX;
        gW1t[ch * W1IMG + c * W1S + k] = W1[(size_t)(k + 1) * Hh + ch * CHUNK + c];
    }
    for (int i = tid; i < Dd * Hh; i += stride) {
        int d = i / Hh;
        int k = i % Hh;
        gW2t[d * W2S + k] = W2[(size_t)k * Dd + d];
    }
}

// ---------------- main persistent rollout kernel ----------------
__global__ void __launch_bounds__(THREADS, 1) sim_rollout_kernel(
    const float* __restrict__ X0, const float* __restrict__ V0,
    const float* __restrict__ Y,  const float* __restrict__ theta,
    const float* __restrict__ W1, const float* __restrict__ b1,
    const float* __restrict__ W2, const float* __restrict__ b2,
    const float* __restrict__ noise, const int* __restrict__ obs_index,
    float* __restrict__ out)
{
    extern __shared__ float sm[];
    float* sW2t = sm + OFF_W2T;
    float* sW1  = sm + OFF_W1;
    float* sX   = sm + OFF_X;
    float* sH   = sm + OFF_H;
    float* sB1  = sm + OFF_B1;
    float* sW0  = sm + OFF_W0;

    const int tid = threadIdx.x;
    const int w   = tid >> 5;
    const int l   = tid & 31;
    const int row0 = blockIdx.x * Rr;

    // warp owns 8 consecutive rows [w*8, w*8+8); thread: 4 consecutive rows, 4 cols stride 16
    const int rg2 = l >> 4;              // 0..1
    const int cq  = l & 15;              // 0..15
    const int r0  = w * 8 + rg2 * 4;     // rows r0..r0+3
    // cols/d: cq + 16*j, j = 0..3

    const float dt   = 1.0f / (float)Mm;
    const float sqdt = sqrtf(dt);
    const int obs = *obs_index;

    // ---- one-time staging ----
    for (int idx = tid; idx < W2SZ / 4; idx += THREADS)
        ((float4*)sW2t)[idx] = ((const float4*)gW2t)[idx];
    for (int idx = tid; idx < Rr * Dd; idx += THREADS) {
        int r = idx >> 6, d = idx & 63;
        sX[r * XS + d] = X0[(size_t)(row0 + r) * Dd + d];
    }
    for (int idx = tid; idx < Rr * Pp; idx += THREADS) {
        int r = idx >> 5, p = idx & 31;
        sX[r * XS + 64 + p] = Y[(size_t)(row0 + r) * Pp + obs * Pp + p];
    }
    for (int idx = tid; idx < Hh; idx += THREADS) {
        sB1[idx] = b1[idx];
        sW0[idx] = W1[idx];              // W1 row 0 (s-column weights)
    }

    // per-thread constants over the 4 d-columns (cq + 16j)
    float thc[4], b2c[4];
    #pragma unroll
    for (int j = 0; j < 4; j++) {
        thc[j] = theta[cq + 16 * j];
        b2c[j] = b2[cq + 16 * j];
    }
    // V state lives in registers of lanes with cq == 0
    float vreg[4];
    #pragma unroll
    for (int i = 0; i < 4; i++) vreg[i] = V0[row0 + r0 + i];

    // prime cp.async: chunk 0 -> buffer 0
    const uint32_t w1sa = (uint32_t)__cvta_generic_to_shared(sW1);
    for (int idx = tid; idx < W1IMG / 4; idx += THREADS)
        cp16(w1sa + idx * 16, gW1t + idx * 4);
    CP_COMMIT();

    const float* aP1 = sX + r0 * XS;
    const float* aP2 = sH + r0 * HS;

    // ---- 50-step rollout ----
    for (int m = 0; m < Mm; ++m) {
        const float s = (float)m * dt;

        // this step's noise (DRAM; hidden behind GEMMs)
        float nz[4][4];
        const float* nb = noise + ((size_t)m * Nn + row0) * Dd;
        #pragma unroll
        for (int i = 0; i < 4; i++)
            #pragma unroll
            for (int j = 0; j < 4; j++)
                nz[i][j] = nb[(size_t)(r0 + i) * Dd + cq + 16 * j];

        u64 zacc[4][4];
        #pragma unroll
        for (int i = 0; i < 4; i++)
            #pragma unroll
            for (int j = 0; j < 4; j++) zacc[i][j] = 0ull;

        for (int ch = 0; ch < NCHUNK; ++ch) {
            // prefetch next chunk's W1 image into the other buffer
            {
                int nxt = (ch + 1) & 7;
                uint32_t dst = w1sa + (uint32_t)(((ch + 1) & 1) * W1IMG) * 4u;
                const float* src = gW1t + nxt * W1IMG;
                for (int idx = tid; idx < W1IMG / 4; idx += THREADS)
                    cp16(dst + idx * 16, src + idx * 4);
                CP_COMMIT();
            }
            CP_WAIT1();
            __syncthreads();     // W1 buffer ready; everyone past previous chunk

            const float* w1b = sW1 + (ch & 1) * W1IMG + cq * W1S;

            // per-chunk h-bias: s*W1[0][c] + b1[c]
            float hb[4];
            #pragma unroll
            for (int j = 0; j < 4; j++) {
                int c = ch * CHUNK + cq + 16 * j;
                hb[j] = s * sW0[c] + sB1[c];
            }

            // ---- GEMM1: h = Xin[8x96 per warp] @ W1chunk ----
            u64 acc[4][4];
            #pragma unroll
            for (int i = 0; i < 4; i++)
                #pragma unroll
                for (int j = 0; j < 4; j++) acc[i][j] = 0ull;

            #pragma unroll 8
            for (int q = 0; q < KX / 4; ++q) {
                ulonglong2 A[4], B[4];
                #pragma unroll
                for (int i = 0; i < 4; i++)          // 2 distinct addrs/warp: broadcast
                    A[i] = *(const ulonglong2*)(aP1 + i * XS + q * 4);
                #pragma unroll
                for (int j = 0; j < 4; j++)          // 16 distinct, stride ≡ 4 mod 32
                    B[j] = *(const ulonglong2*)(w1b + j * 16 * W1S + q * 4);
                #pragma unroll
                for (int i = 0; i < 4; i++)
                    #pragma unroll
                    for (int j = 0; j < 4; j++) {
                        fma2(acc[i][j], A[i].x, B[j].x);
                        fma2(acc[i][j], A[i].y, B[j].y);
                    }
            }

            // bias + tanh -> sH (warp-local rows)
            #pragma unroll
            for (int i = 0; i < 4; i++)
                #pragma unroll
                for (int j = 0; j < 4; j++) {
                    float2 t = upk(acc[i][j]);
                    sH[(r0 + i) * HS + cq + 16 * j] = fast_tanh(t.x + t.y + hb[j]);
                }
            __syncwarp();        // h rows are warp-owned: no block barrier needed

            // ---- GEMM2: Z += h[8x64 per warp] @ W2chunk ----
            const float* w2b = sW2t + cq * W2S + ch * CHUNK;
            #pragma unroll 8
            for (int q = 0; q < CHUNK / 4; ++q) {
                ulonglong2 A[4], B[4];
                #pragma unroll
                for (int i = 0; i < 4; i++)
                    A[i] = *(const ulonglong2*)(aP2 + i * HS + q * 4);
                #pragma unroll
                for (int j = 0; j < 4; j++)
                    B[j] = *(const ulonglong2*)(w2b + j * 16 * W2S + q * 4);
                #pragma unroll
                for (int i = 0; i < 4; i++)
                    #pragma unroll
                    for (int j = 0; j < 4; j++) {
                        fma2(zacc[i][j], A[i].x, B[j].x);
                        fma2(zacc[i][j], A[i].y, B[j].y);
                    }
            }
        }

        // ---- epilogue: V and X updates (all warp-local) ----
        #pragma unroll
        for (int i = 0; i < 4; i++) {
            float vpart = 0.0f;
            #pragma unroll
            for (int j = 0; j < 4; j++) {
                float2 t = upk(zacc[i][j]);
                float z  = t.x + t.y + b2c[j];
                float wm = sqdt * nz[i][j];
                vpart += z * wm - 0.5f * dt * z * z;
                float* xp = &sX[(r0 + i) * XS + cq + 16 * j];
                float xo = *xp;
                *xp = xo + dt * (thc[j] - xo - z) + wm;
            }
            // reduce over the 16 lanes of this row group
            vpart += __shfl_down_sync(0xffffffffu, vpart, 8, 16);
            vpart += __shfl_down_sync(0xffffffffu, vpart, 4, 16);
            vpart += __shfl_down_sync(0xffffffffu, vpart, 2, 16);
            vpart += __shfl_down_sync(0xffffffffu, vpart, 1, 16);
            vreg[i] += vpart;    // only meaningful at cq == 0
        }
        __syncwarp();            // X rows warp-owned: order STS before next step's LDS
    }

    __syncthreads();
    // ---- output: X then V ----
    for (int idx = tid; idx < Rr * Dd; idx += THREADS) {
        int r = idx >> 6, d = idx & 63;
        out[(size_t)(row0 + r) * Dd + d] = sX[r * XS + d];
    }
    if (cq == 0) {
        #pragma unroll
        for (int i = 0; i < 4; i++)
            out[(size_t)Nn * Dd + row0 + r0 + i] = vreg[i];
    }
}

extern "C" void kernel_launch(void* const* d_in, const int* in_sizes, int n_in,
                              void* d_out, int out_size)
{
    (void)in_sizes; (void)n_in; (void)out_size;
    cudaFuncSetAttribute(sim_rollout_kernel,
                         cudaFuncAttributeMaxDynamicSharedMemorySize, SMEM_BYTES);

    transpose_weights<<<64, 256>>>((const float*)d_in[4], (const float*)d_in[6]);
    sim_rollout_kernel<<<NBLOCKS, THREADS, SMEM_BYTES>>>(
        (const float*)d_in[0], (const float*)d_in[1], (const float*)d_in[2],
        (const float*)d_in[3], (const float*)d_in[4], (const float*)d_in[5],
        (const float*)d_in[6], (const float*)d_in[7], (const float*)d_in[8],
        (const int*)d_in[9],   (float*)d_out);
}